// round 8
// baseline (speedup 1.0000x reference)
#include <cuda_runtime.h>

#define BATCH 65536
#define NEG 5
#define WPB 8
#define THREADS 256
#define GRID 740                  // 148 SMs * 5 blocks -> one wave at <=51 regs
#define TW (GRID * WPB)           // 5920 warps

__device__ float g_partials[GRID];
__device__ unsigned int g_done_count = 0;

struct Idx { int w, p, n0, n1, n2, n3, n4; };

__device__ __forceinline__ Idx load_idx(
    int b, const int* __restrict__ pos_w, const int* __restrict__ pos_v,
    const int* __restrict__ neg_v)
{
    Idx I;                              // 32-bit row offsets (max 3.2M float4)
    I.w  = pos_w[b] << 5;
    I.p  = pos_v[b] << 5;
    I.n0 = neg_v[b * NEG + 0] << 5;
    I.n1 = neg_v[b * NEG + 1] << 5;
    I.n2 = neg_v[b * NEG + 2] << 5;
    I.n3 = neg_v[b * NEG + 3] << 5;
    I.n4 = neg_v[b * NEG + 4] << 5;
    return I;
}

__global__ __launch_bounds__(THREADS, 5) void sgneg_fused(
    const int* __restrict__ pos_w,
    const int* __restrict__ pos_v,
    const int* __restrict__ neg_v,
    const float4* __restrict__ w_table,
    const float4* __restrict__ v_table,
    float* __restrict__ out)
{
    const int lane = threadIdx.x & 31;
    const int wib  = threadIdx.x >> 5;
    const int gw   = blockIdx.x * WPB + wib;
    const unsigned FULL = 0xFFFFFFFFu;

    float acc = 0.0f;

    int b = gw;                                  // gw < 5920 < BATCH always
    Idx I = load_idx(b, pos_w, pos_v, neg_v);    // prologue idx fetch

    while (b < BATCH) {
        // 1) Issue the 7 gathers for the CURRENT element (512B coalesced each)
        const float4 w  = w_table[I.w  + lane];
        const float4 p  = v_table[I.p  + lane];
        const float4 n0 = v_table[I.n0 + lane];
        const float4 n1 = v_table[I.n1 + lane];
        const float4 n2 = v_table[I.n2 + lane];
        const float4 n3 = v_table[I.n3 + lane];
        const float4 n4 = v_table[I.n4 + lane];

        // 2) Prefetch NEXT element's indices under the gather latency
        const int bn = b + TW;
        if (bn < BATCH) I = load_idx(bn, pos_w, pos_v, neg_v);

        // 3) Process current element
        float d0 = w.x*p.x  + w.y*p.y  + w.z*p.z  + w.w*p.w;
        float d1 = w.x*n0.x + w.y*n0.y + w.z*n0.z + w.w*n0.w;
        float d2 = w.x*n1.x + w.y*n1.y + w.z*n1.z + w.w*n1.w;
        float d3 = w.x*n2.x + w.y*n2.y + w.z*n2.z + w.w*n2.w;
        float d4 = w.x*n3.x + w.y*n3.y + w.z*n3.z + w.w*n3.w;
        float d5 = w.x*n4.x + w.y*n4.y + w.z*n4.z + w.w*n4.w;

        // Packed 6-value warp reduction: 13 shuffles.
        float t, u;
        t = __shfl_xor_sync(FULL, d0, 16);
        u = __shfl_xor_sync(FULL, d1, 16);
        float e0 = (lane & 16) ? d1 + u : d0 + t;
        t = __shfl_xor_sync(FULL, d2, 16);
        u = __shfl_xor_sync(FULL, d3, 16);
        float e1 = (lane & 16) ? d3 + u : d2 + t;
        t = __shfl_xor_sync(FULL, d4, 16);
        u = __shfl_xor_sync(FULL, d5, 16);
        float e2 = (lane & 16) ? d5 + u : d4 + t;
        t = __shfl_xor_sync(FULL, e0, 8);
        u = __shfl_xor_sync(FULL, e1, 8);
        float f0 = (lane & 8) ? e1 + u : e0 + t;
        e2 += __shfl_xor_sync(FULL, e2, 8);
        t = __shfl_xor_sync(FULL, f0, 4);
        u = __shfl_xor_sync(FULL, e2, 4);
        float g = (lane & 4) ? e2 + u : f0 + t;
        g += __shfl_xor_sync(FULL, g, 2);
        g += __shfl_xor_sync(FULL, g, 1);

        // Owner lanes: 0->pos, 16,8,24,4,20 -> negatives
        const bool active = ((lane & 3) == 0) && !((lane & 4) && (lane & 8));
        float x = fminf(fmaxf(g, -10.0f), 10.0f);
        if (lane != 0) x = -x;
        float term = -__logf(1.0f + __expf(-x));   // log_sigmoid, x in [-10,10]
        acc += active ? term : 0.0f;

        b = bn;
    }

    // Single end-of-kernel warp reduction
#pragma unroll
    for (int off = 16; off > 0; off >>= 1)
        acc += __shfl_xor_sync(FULL, acc, off);

    __shared__ float sh[WPB];
    if (lane == 0) sh[wib] = acc;
    __syncthreads();

    __shared__ bool is_last;
    if (threadIdx.x == 0) {
        float s = 0.0f;
#pragma unroll
        for (int i = 0; i < WPB; i++) s += sh[i];
        g_partials[blockIdx.x] = s;
        __threadfence();
        unsigned int old = atomicAdd(&g_done_count, 1u);
        is_last = (old == (unsigned int)(GRID - 1));
    }
    __syncthreads();

    if (is_last) {
        __shared__ double shd[THREADS];
        double s = 0.0;
        for (int i = threadIdx.x; i < GRID; i += THREADS)
            s += (double)g_partials[i];
        shd[threadIdx.x] = s;
        __syncthreads();
#pragma unroll
        for (int st = THREADS / 2; st > 0; st >>= 1) {
            if (threadIdx.x < st) shd[threadIdx.x] += shd[threadIdx.x + st];
            __syncthreads();
        }
        if (threadIdx.x == 0) {
            out[0] = (float)(-shd[0]);
            g_done_count = 0;   // reset for next graph replay
        }
    }
}

extern "C" void kernel_launch(void* const* d_in, const int* in_sizes, int n_in,
                              void* d_out, int out_size)
{
    const int*    pos_w   = (const int*)d_in[0];
    const int*    pos_v   = (const int*)d_in[1];
    const int*    neg_v   = (const int*)d_in[2];
    const float4* w_table = (const float4*)d_in[3];
    const float4* v_table = (const float4*)d_in[4];
    float*        out     = (float*)d_out;

    sgneg_fused<<<GRID, THREADS>>>(pos_w, pos_v, neg_v, w_table, v_table, out);
}

// round 9
// speedup vs baseline: 1.4444x; 1.4444x over previous
#include <cuda_runtime.h>

#define BATCH 65536
#define NEG 5
#define WPB 8
#define THREADS 256
#define GRID 1184                 // 148 SMs * 8 blocks -> one wave at 32 regs
#define TW (GRID * WPB)           // 9472 warps

__device__ float g_partials[GRID];
__device__ unsigned int g_done_count = 0;

__global__ __launch_bounds__(THREADS, 8) void sgneg_fused(
    const int* __restrict__ pos_w,
    const int* __restrict__ pos_v,
    const int* __restrict__ neg_v,
    const float4* __restrict__ w_table,
    const float4* __restrict__ v_table,
    float* __restrict__ out)
{
    const int lane = threadIdx.x & 31;
    const int wib  = threadIdx.x >> 5;
    const int gw   = blockIdx.x * WPB + wib;
    const unsigned FULL = 0xFFFFFFFFu;

    float acc = 0.0f;

    for (int b = gw; b < BATCH; b += TW) {
        // Indices: uniform per warp (broadcast loads), 32-bit row offsets
        const int wi  = pos_w[b] << 5;
        const int pvi = pos_v[b] << 5;
        const int ni0 = neg_v[b * NEG + 0] << 5;
        const int ni1 = neg_v[b * NEG + 1] << 5;
        const int ni2 = neg_v[b * NEG + 2] << 5;
        const int ni3 = neg_v[b * NEG + 3] << 5;
        const int ni4 = neg_v[b * NEG + 4] << 5;

        // 7 independent 512B coalesced gathers
        const float4 w  = w_table[wi  + lane];
        const float4 p  = v_table[pvi + lane];
        const float4 n0 = v_table[ni0 + lane];
        const float4 n1 = v_table[ni1 + lane];
        const float4 n2 = v_table[ni2 + lane];
        const float4 n3 = v_table[ni3 + lane];
        const float4 n4 = v_table[ni4 + lane];

        float d0 = w.x*p.x  + w.y*p.y  + w.z*p.z  + w.w*p.w;
        float d1 = w.x*n0.x + w.y*n0.y + w.z*n0.z + w.w*n0.w;
        float d2 = w.x*n1.x + w.y*n1.y + w.z*n1.z + w.w*n1.w;
        float d3 = w.x*n2.x + w.y*n2.y + w.z*n2.z + w.w*n2.w;
        float d4 = w.x*n3.x + w.y*n3.y + w.z*n3.z + w.w*n3.w;
        float d5 = w.x*n4.x + w.y*n4.y + w.z*n4.z + w.w*n4.w;

        // Packed 6-value warp reduction: 13 shuffles.
        float t, u;
        t = __shfl_xor_sync(FULL, d0, 16);
        u = __shfl_xor_sync(FULL, d1, 16);
        float e0 = (lane & 16) ? d1 + u : d0 + t;
        t = __shfl_xor_sync(FULL, d2, 16);
        u = __shfl_xor_sync(FULL, d3, 16);
        float e1 = (lane & 16) ? d3 + u : d2 + t;
        t = __shfl_xor_sync(FULL, d4, 16);
        u = __shfl_xor_sync(FULL, d5, 16);
        float e2 = (lane & 16) ? d5 + u : d4 + t;
        t = __shfl_xor_sync(FULL, e0, 8);
        u = __shfl_xor_sync(FULL, e1, 8);
        float f0 = (lane & 8) ? e1 + u : e0 + t;
        e2 += __shfl_xor_sync(FULL, e2, 8);
        t = __shfl_xor_sync(FULL, f0, 4);
        u = __shfl_xor_sync(FULL, e2, 4);
        float g = (lane & 4) ? e2 + u : f0 + t;
        g += __shfl_xor_sync(FULL, g, 2);
        g += __shfl_xor_sync(FULL, g, 1);

        // Owner lanes: 0->pos, 16,8,24,4,20 -> negatives
        const bool active = ((lane & 3) == 0) && !((lane & 4) && (lane & 8));
        float x = fminf(fmaxf(g, -10.0f), 10.0f);
        if (lane != 0) x = -x;
        float term = -__logf(1.0f + __expf(-x));   // log_sigmoid, x in [-10,10]
        acc += active ? term : 0.0f;
    }

    // Single end-of-kernel warp reduction
#pragma unroll
    for (int off = 16; off > 0; off >>= 1)
        acc += __shfl_xor_sync(FULL, acc, off);

    __shared__ float sh[WPB];
    if (lane == 0) sh[wib] = acc;
    __syncthreads();

    __shared__ bool is_last;
    if (threadIdx.x == 0) {
        float s = 0.0f;
#pragma unroll
        for (int i = 0; i < WPB; i++) s += sh[i];
        g_partials[blockIdx.x] = s;
        __threadfence();
        unsigned int old = atomicAdd(&g_done_count, 1u);
        is_last = (old == (unsigned int)(GRID - 1));
    }
    __syncthreads();

    if (is_last) {
        __shared__ double shd[THREADS];
        double s = 0.0;
        for (int i = threadIdx.x; i < GRID; i += THREADS)
            s += (double)g_partials[i];
        shd[threadIdx.x] = s;
        __syncthreads();
#pragma unroll
        for (int st = THREADS / 2; st > 0; st >>= 1) {
            if (threadIdx.x < st) shd[threadIdx.x] += shd[threadIdx.x + st];
            __syncthreads();
        }
        if (threadIdx.x == 0) {
            out[0] = (float)(-shd[0]);
            g_done_count = 0;   // reset for next graph replay
        }
    }
}

extern "C" void kernel_launch(void* const* d_in, const int* in_sizes, int n_in,
                              void* d_out, int out_size)
{
    const int*    pos_w   = (const int*)d_in[0];
    const int*    pos_v   = (const int*)d_in[1];
    const int*    neg_v   = (const int*)d_in[2];
    const float4* w_table = (const float4*)d_in[3];
    const float4* v_table = (const float4*)d_in[4];
    float*        out     = (float*)d_out;

    sgneg_fused<<<GRID, THREADS>>>(pos_w, pos_v, neg_v, w_table, v_table, out);
}